// round 14
// baseline (speedup 1.0000x reference)
#include <cuda_runtime.h>
#include <cuda_fp16.h>
#include <cstddef>

// ForwardSim, fully tensorized HMMA (sm_103 baseline mma.sync).
// R14 = R13 with the output-row indexing fix (row0 double-counted g).
// Warp-pair tiles: each pair owns 32 rows; warp ch owns 32 rows x 64 cols.
// Halves B-fragment/BW smem traffic per row; one 64-thread named barrier +
// 256B double-buffered PART exchange per step. GEMM2 2-term fp16 split;
// GEMM1 k8 3-term + exact fp32 feature-8 FMA; per-q env loads; no prefetch.

using u32 = unsigned int;
using u64 = unsigned long long;

namespace {
constexpr int kB = 32768, kT = 50, kH = 128, kThreads = 256;
constexpr int GRID = 296;            // 2 x 148 SMs
constexpr int NT32 = kB / 32;        // 1024 pair-tiles of 32 rows

constexpr int OFF_BFRAG = 0;         // 32768: W2 hi frags [kb][nf2][lane] 16B
constexpr int OFF_PACC  = 32768;     // 65536: projAcc frags [pp][mi][nf1][lane]
constexpr int OFF_W1EB  = 98304;     // 4096:  W1e k8 B-frags [nf1][lane] 8B
constexpr int OFF_W72   = 102400;    // 512:   W1 row 72 natural
constexpr int OFF_BW    = 102912;    // 1024:  (b2 pair, W3 pair) per col pair
constexpr int OFF_PART  = 103936;    // 2048:  [buf][pp][ch][32] f32
constexpr int SMEM_BYTES = 105984;
constexpr int OFF_W1P   = 0;         // phase alias in BFRAG: W1[0:64] natural
} // namespace

__device__ __forceinline__ u64 pack_dup(float v) {
    u64 r; asm("mov.b64 %0, {%1, %1};" : "=l"(r) : "f"(v)); return r;
}
__device__ __forceinline__ u64 pack2(float a, float b) {
    u64 r; asm("mov.b64 %0, {%1, %2};" : "=l"(r) : "f"(a), "f"(b)); return r;
}
__device__ __forceinline__ void unpack2(u64 v, float& a, float& b) {
    asm("mov.b64 {%0, %1}, %2;" : "=f"(a), "=f"(b) : "l"(v));
}
__device__ __forceinline__ u64 fma2(u64 a, u64 b, u64 c) {
    u64 d; asm("fma.rn.f32x2 %0, %1, %2, %3;" : "=l"(d) : "l"(a), "l"(b), "l"(c));
    return d;
}
__device__ __forceinline__ void split2(float f0, float f1, u32& hi, u32& lo) {
    __half h0 = __float2half_rn(f0), h1 = __float2half_rn(f1);
    __half2 hh = __halves2half2(h0, h1);
    hi = reinterpret_cast<u32&>(hh);
    __half2 ll = __floats2half2_rn(f0 - __half2float(h0),
                                   f1 - __half2float(h1));
    lo = reinterpret_cast<u32&>(ll);
}
__device__ __forceinline__ u32 hi2only(float f0, float f1) {
    __half2 hh = __floats2half2_rn(f0, f1);
    return reinterpret_cast<u32&>(hh);
}
__device__ __forceinline__ void mma16816(float d[4], u32 a0, u32 a1, u32 a2,
                                         u32 a3, u32 b0, u32 b1) {
    asm volatile(
        "mma.sync.aligned.m16n8k16.row.col.f32.f16.f16.f32 "
        "{%0,%1,%2,%3}, {%4,%5,%6,%7}, {%8,%9}, {%0,%1,%2,%3};"
        : "+f"(d[0]), "+f"(d[1]), "+f"(d[2]), "+f"(d[3])
        : "r"(a0), "r"(a1), "r"(a2), "r"(a3), "r"(b0), "r"(b1));
}
__device__ __forceinline__ void mma1688(float d[4], u32 a0, u32 a1, u32 b0) {
    asm volatile(
        "mma.sync.aligned.m16n8k8.row.col.f32.f16.f16.f32 "
        "{%0,%1,%2,%3}, {%4,%5}, {%6}, {%0,%1,%2,%3};"
        : "+f"(d[0]), "+f"(d[1]), "+f"(d[2]), "+f"(d[3])
        : "r"(a0), "r"(a1), "r"(b0));
}
#define BAR_PAIR(id) asm volatile("bar.sync %0, 64;" :: "r"(id) : "memory")

__global__ void __launch_bounds__(kThreads, 2)
fsim_mma(const float* __restrict__ proj, const float* __restrict__ idm,
         const float* __restrict__ merg, const float* __restrict__ W1,
         const float* __restrict__ b1,   const float* __restrict__ W2,
         const float* __restrict__ b2,   const float* __restrict__ W3,
         const float* __restrict__ b3,   const float* __restrict__ smean,
         const float* __restrict__ svar, float* __restrict__ out)
{
    extern __shared__ char smem[];
    float* smf = (float*)smem;

    const int tid = threadIdx.x, w = tid >> 5, lane = tid & 31;
    const int g = lane >> 2, q = lane & 3;
    const int bx = blockIdx.x;
    const int wp = w >> 1, ch = w & 1;
    const int pp = (wp - bx) & 3;               // rotated pair slot
    const int tileId = pp * GRID + bx;          // 32-row tile
    const bool active = tileId < NT32;

    // ---------------- phase A: stage W1[0:64] natural + tables -------------
    for (int i = tid; i < 64 * kH; i += kThreads)
        smf[(OFF_W1P >> 2) + i] = W1[i];
    if (tid < 64) {
        int c = tid * 2;
        float4 v;
        v.x = b2[c]; v.y = b2[c + 1]; v.z = W3[c]; v.w = W3[c + 1];
        *(float4*)(smem + OFF_BW + tid * 16) = v;
    }
    if (tid < 128)
        smf[(OFF_W72 >> 2) + tid] = W1[(size_t)72 * 128 + tid];
    __syncthreads();

    // -------- phase B: projAcc = proj@W1[:64]+b1 -> fragment-native fp32 ---
    for (int task = tid; task < 1024; task += kThreads) {
        int t_pp = task >> 8, rem = task & 255;
        int lr = rem >> 3, cg = rem & 7;        // row-in-tile 0..31, col group
        int tId = t_pp * GRID + bx;
        if (tId >= NT32) continue;
        const float* prow = proj + (size_t)(tId * 32 + lr) * 64;
        u64 acc[8];
        #pragma unroll
        for (int e = 0; e < 8; e++)
            acc[e] = pack2(__ldg(&b1[cg * 16 + 2 * e]),
                           __ldg(&b1[cg * 16 + 2 * e + 1]));
        #pragma unroll 4
        for (int k4 = 0; k4 < 16; k4++) {
            float4 av = __ldg((const float4*)(prow + k4 * 4));
            float avv[4] = {av.x, av.y, av.z, av.w};
            #pragma unroll
            for (int e2 = 0; e2 < 4; e2++) {
                u64 a = pack_dup(avv[e2]);
                const u64* ww = (const u64*)
                    &smf[(OFF_W1P >> 2) + (k4 * 4 + e2) * 128 + cg * 16];
                #pragma unroll
                for (int e = 0; e < 8; e++) acc[e] = fma2(a, ww[e], acc[e]);
            }
        }
        int mi = lr >> 4, half = (lr >> 3) & 1, lrow = lr & 7;
        #pragma unroll
        for (int e = 0; e < 8; e++) {
            int nf1 = cg * 2 + (e >> 2);
            int ln  = lrow * 4 + (e & 3);
            float lo_, hi_;
            unpack2(acc[e], lo_, hi_);
            *(float2*)(smem + OFF_PACC +
                       (size_t)((((t_pp * 2 + mi) * 16 + nf1) * 32 + ln) * 16)
                       + half * 8) = make_float2(lo_, hi_);
        }
    }
    __syncthreads();

    // ---- phase C: W2 -> hi-only frags packed per nf-pair (overwrites W1P) -
    for (int i = tid; i < 2048; i += kThreads) {
        int t  = i & 31, nf2 = (i >> 5) & 7, kb = (i >> 8) & 7;
        int gg = t >> 2, qq = t & 3;
        int k0 = kb * 16 + qq * 2;
        int nA = nf2 * 16 + gg;
        int nB = nA + 8;
        u32 hA0 = hi2only(W2[(size_t)k0 * 128 + nA],
                          W2[(size_t)(k0 + 1) * 128 + nA]);
        u32 hA1 = hi2only(W2[(size_t)(k0 + 8) * 128 + nA],
                          W2[(size_t)(k0 + 9) * 128 + nA]);
        u32 hB0 = hi2only(W2[(size_t)k0 * 128 + nB],
                          W2[(size_t)(k0 + 1) * 128 + nB]);
        u32 hB1 = hi2only(W2[(size_t)(k0 + 8) * 128 + nB],
                          W2[(size_t)(k0 + 9) * 128 + nB]);
        ulonglong2 e;
        e.x = ((u64)hA1 << 32) | hA0;
        e.y = ((u64)hB1 << 32) | hB0;
        *(ulonglong2*)(smem + OFF_BFRAG +
                       (size_t)((kb * 8 + nf2) * 32 + t) * 16) = e;
    }
    // -------- phase C2: W1e rows 64..71 -> k8 B-frags [hi u32 | lo u32] ----
    for (int i = tid; i < 512; i += kThreads) {
        int t = i & 31, nf = i >> 5;        // nf1 0..15
        int gg = t >> 2, qq = t & 3;
        int n  = nf * 8 + gg;
        int k0 = qq * 2;
        float w00 = W1[(size_t)(64 + k0) * 128 + n];
        float w01 = W1[(size_t)(64 + k0 + 1) * 128 + n];
        u32 h, l;
        split2(w00, w01, h, l);
        *(u64*)(smem + OFF_W1EB + (size_t)(nf * 32 + t) * 8) =
            ((u64)l << 32) | h;
    }
    __syncthreads();

    if (!active) return;

    // ---------------- per-lane constants ----------------
    const float b3v = __ldg(&b3[0]);
    const int tbase = tileId * 32;        // tile row base (lane rows: +lro)
    // scaler consts for features 2q, 2q+1 (q==3 -> mc passthrough)
    float scm0 = 0.f, scm1 = 0.f, sci0 = 1.f, sci1 = 1.f;
    if (q < 3) {
        scm0 = __ldg(&smean[2 * q]);
        scm1 = __ldg(&smean[2 * q + 1]);
        sci0 = rsqrtf(__ldg(&svar[2 * q]));
        sci1 = rsqrtf(__ldg(&svar[2 * q + 1]));
    }
    const int idxA = (q == 2) ? 2 : 1;
    const int idxB = (q == 2) ? 5 : (q == 1) ? 4 : 1;
    const int barId = 1 + pp;

    float egv[4], egx[4], act[4] = {0.f, 0.f, 0.f, 0.f};

    // ================= timestep loop =================
    for (int t = 0; t < kT; t++) {
        // ---- env features for this lane's 4 rows (only what q needs) ----
        u32 ehi[4], elo[4];
        float e8[4];
        #pragma unroll
        for (int i = 0; i < 4; i++) {
            int row = tbase + (i >> 1) * 16 + (i & 1) * 8 + g;
            const float* bi = idm + (size_t)row * (kT * 12) + t * 12;
            const float* mi_ = merg + (size_t)row * (kT * 3) + t * 3;
            float vA = (q == 3) ? __ldg(mi_)     : __ldg(bi + idxA);
            float vB = (q == 3) ? __ldg(mi_ + 1) : __ldg(bi + idxB);
            float vC = __ldg(bi + 11);
            e8[i] = __ldg(mi_ + 2);
            if (t == 0) {
                egv[i] = __ldg(bi);
                egx[i] = __ldg(bi + 3);
            } else {
                egv[i] = fmaf(act[i], 0.1f, egv[i]);
                egx[i] = egx[i] + egv[i] * 0.1f + act[i] * 0.005f;
            }
            float tmpa = egv[i] - vA;
            float tmpb = vB - egx[i];
            float fa = (q == 0) ? egv[i] : (q == 1) ? tmpa
                       : (q == 2) ? tmpa * vC : vA;
            float fb = (q == 0) ? vA : (q == 1) ? tmpb
                       : (q == 2) ? fmaf(tmpb, vC, (1.0f - vC) * 100.0f) : vB;
            fa = (fa - scm0) * sci0;
            fb = (fb - scm1) * sci1;
            split2(fa, fb, ehi[i], elo[i]);
        }

        float d[2][8][4];
        #pragma unroll
        for (int mi = 0; mi < 2; mi++)
            #pragma unroll
            for (int nf = 0; nf < 8; nf++)
                d[mi][nf][0] = d[mi][nf][1] = d[mi][nf][2] = d[mi][nf][3] = 0.f;

        for (int kb = 0; kb < 8; kb++) {
            int nf1 = kb * 2;
            u64 bA = *(const u64*)(smem + OFF_W1EB +
                (size_t)((nf1 * 32 + lane) * 8));
            u64 bB = *(const u64*)(smem + OFF_W1EB +
                (size_t)(((nf1 + 1) * 32 + lane) * 8));
            float2 wA = *(const float2*)(smem + OFF_W72 + (nf1 * 4 + q) * 8);
            float2 wB = *(const float2*)(smem + OFF_W72 + ((nf1 + 1) * 4 + q) * 8);
            u32 hA = (u32)bA, lA = (u32)(bA >> 32);
            u32 hB = (u32)bB, lB = (u32)(bB >> 32);

            u32 Ah[2][4], Al[2][4];
            #pragma unroll
            for (int mi = 0; mi < 2; mi++) {
                float4 pv0 = *(const float4*)(smem + OFF_PACC +
                    (size_t)((((pp * 2 + mi) * 16 + nf1) * 32 + lane) * 16));
                float4 pv1 = *(const float4*)(smem + OFF_PACC +
                    (size_t)((((pp * 2 + mi) * 16 + nf1 + 1) * 32 + lane) * 16));
                const int i0 = mi * 2, i1 = mi * 2 + 1;
                float dd0[4], dd1[4];
                dd0[0] = fmaf(e8[i0], wA.x, pv0.x);
                dd0[1] = fmaf(e8[i0], wA.y, pv0.y);
                dd0[2] = fmaf(e8[i1], wA.x, pv0.z);
                dd0[3] = fmaf(e8[i1], wA.y, pv0.w);
                dd1[0] = fmaf(e8[i0], wB.x, pv1.x);
                dd1[1] = fmaf(e8[i0], wB.y, pv1.y);
                dd1[2] = fmaf(e8[i1], wB.x, pv1.z);
                dd1[3] = fmaf(e8[i1], wB.y, pv1.w);
                mma1688(dd0, ehi[i0], ehi[i1], hA);
                mma1688(dd1, ehi[i0], ehi[i1], hB);
                mma1688(dd0, elo[i0], elo[i1], hA);   // lo*hi
                mma1688(dd1, elo[i0], elo[i1], hB);
                mma1688(dd0, ehi[i0], ehi[i1], lA);   // hi*lo
                mma1688(dd1, ehi[i0], ehi[i1], lB);
                u32 h01, l01, h23, l23;
                split2(fmaxf(dd0[0], 0.f), fmaxf(dd0[1], 0.f), h01, l01);
                split2(fmaxf(dd0[2], 0.f), fmaxf(dd0[3], 0.f), h23, l23);
                Ah[mi][0] = h01; Al[mi][0] = l01;
                Ah[mi][1] = h23; Al[mi][1] = l23;
                split2(fmaxf(dd1[0], 0.f), fmaxf(dd1[1], 0.f), h01, l01);
                split2(fmaxf(dd1[2], 0.f), fmaxf(dd1[3], 0.f), h23, l23);
                Ah[mi][2] = h01; Al[mi][2] = l01;
                Ah[mi][3] = h23; Al[mi][3] = l23;
            }

            // ---- GEMM2 (2-term): this warp's 64 cols via 4 nf2-pairs ----
            const char* bfp = smem + OFF_BFRAG +
                              (size_t)((kb * 8 + ch * 4)) * 512 + lane * 16;
            #pragma unroll
            for (int nf2 = 0; nf2 < 4; nf2++) {
                ulonglong2 bf = *(const ulonglong2*)(bfp + nf2 * 512);
                u32 hA0 = (u32)bf.x, hA1 = (u32)(bf.x >> 32);
                u32 hB0 = (u32)bf.y, hB1 = (u32)(bf.y >> 32);
                #pragma unroll
                for (int mi = 0; mi < 2; mi++) {
                    mma16816(d[mi][2 * nf2],
                             Ah[mi][0], Ah[mi][1], Ah[mi][2], Ah[mi][3],
                             hA0, hA1);
                    mma16816(d[mi][2 * nf2 + 1],
                             Ah[mi][0], Ah[mi][1], Ah[mi][2], Ah[mi][3],
                             hB0, hB1);
                    mma16816(d[mi][2 * nf2],
                             Al[mi][0], Al[mi][1], Al[mi][2], Al[mi][3],
                             hA0, hA1);
                    mma16816(d[mi][2 * nf2 + 1],
                             Al[mi][0], Al[mi][1], Al[mi][2], Al[mi][3],
                             hB0, hB1);
                }
            }
        }

        // ---- epilogue: relu(D + b2) . W3 over this warp's 64 cols ----
        float s[4] = {0.f, 0.f, 0.f, 0.f};
        #pragma unroll
        for (int nfl = 0; nfl < 8; nfl++) {
            float4 bw = *(const float4*)(smem + OFF_BW +
                                         ((ch * 8 + nfl) * 4 + q) * 16);
            #pragma unroll
            for (int mi = 0; mi < 2; mi++) {
                s[mi * 2]     += fmaxf(d[mi][nfl][0] + bw.x, 0.f) * bw.z +
                                 fmaxf(d[mi][nfl][1] + bw.y, 0.f) * bw.w;
                s[mi * 2 + 1] += fmaxf(d[mi][nfl][2] + bw.x, 0.f) * bw.z +
                                 fmaxf(d[mi][nfl][3] + bw.y, 0.f) * bw.w;
            }
        }
        #pragma unroll
        for (int i = 0; i < 4; i++) {
            s[i] += __shfl_xor_sync(0xFFFFFFFFu, s[i], 1);
            s[i] += __shfl_xor_sync(0xFFFFFFFFu, s[i], 2);
        }
        // ---- pair exchange: PART[buf][pp][ch][32], one barrier ----
        float* part = smf + (OFF_PART >> 2) + (((t & 1) * 4 + pp) * 2) * 32;
        if (q == 0) {
            #pragma unroll
            for (int i = 0; i < 4; i++)
                part[ch * 32 + (i >> 1) * 16 + (i & 1) * 8 + g] = s[i];
        }
        BAR_PAIR(barId);
        #pragma unroll
        for (int i = 0; i < 4; i++) {
            int lro = (i >> 1) * 16 + (i & 1) * 8 + g;
            float a = part[lro] + part[32 + lro] + b3v;
            act[i] = a;
            if (q == 0 && ch == 0)
                out[(size_t)(tbase + lro) * kT + t] = a;
        }
    }
}

extern "C" void kernel_launch(void* const* d_in, const int* in_sizes, int n_in,
                              void* d_out, int out_size)
{
    (void)in_sizes; (void)n_in; (void)out_size;
    const float* proj  = (const float*)d_in[0];
    const float* idm   = (const float*)d_in[1];
    const float* merg  = (const float*)d_in[2];
    const float* W1    = (const float*)d_in[3];
    const float* b1    = (const float*)d_in[4];
    const float* W2    = (const float*)d_in[5];
    const float* b2    = (const float*)d_in[6];
    const float* W3    = (const float*)d_in[7];
    const float* b3    = (const float*)d_in[8];
    const float* smean = (const float*)d_in[9];
    const float* svar  = (const float*)d_in[10];
    float* out = (float*)d_out;

    cudaFuncSetAttribute(fsim_mma, cudaFuncAttributeMaxDynamicSharedMemorySize,
                         SMEM_BYTES);
    fsim_mma<<<GRID, kThreads, SMEM_BYTES>>>(
        proj, idm, merg, W1, b1, W2, b2, W3, b3, smean, svar, out);
}

// round 15
// speedup vs baseline: 1.2308x; 1.2308x over previous
#include <cuda_runtime.h>
#include <cuda_fp16.h>
#include <cstddef>

// ForwardSim, fully tensorized HMMA (sm_103 baseline mma.sync).
// R15 = R12 (best: 487.7us) + SMSP-balanced slot rotation: R12's fixed map
// tileId = w*GRID+bx left warp 7 never-active and warp 6 partial, so SMSP3
// ran 1 active warp/CTA vs 2 on SMSP0-2. slot = (w+bx)&7 rotates the idle
// slots across SMSPs (and differently for the 2 CTAs on an SM), balancing
// ~3.46 active warps per SMSP. Hot loop unchanged: warp-local 16-row
// pipelines, no barriers; GEMM2 2-term fp16 split (A hi+lo, B hi-only);
// GEMM1 k8 3-term + exact fp32 feature-8 FMA; idm/merg prefetch.

using u32 = unsigned int;
using u64 = unsigned long long;

namespace {
constexpr int kB = 32768, kT = 50, kH = 128, kThreads = 256;
constexpr int GRID = 296;            // 2 x 148 SMs
constexpr int NT   = kB / 16;        // 2048 warp-tiles of 16 rows

constexpr int OFF_BFRAG = 0;        // 32768: W2 hi frags [kb][nf2][lane] 16B
constexpr int OFF_PACC  = 32768;    // 65536: projAcc frags [slot][nf1][lane] 16B
constexpr int OFF_W1EB  = 98304;    // 4096:  W1e k8 B-frags [nf1][lane] 8B
constexpr int OFF_W72   = 102400;   // 512:   W1 row 72 natural
constexpr int OFF_BW    = 102912;   // 1024:  (b2 pair, W3 pair) per col pair
constexpr int SMEM_BYTES = 103936;
constexpr int OFF_W1P   = 0;        // phase alias in BFRAG: W1[0:64] natural
} // namespace

__device__ __forceinline__ u64 pack_dup(float v) {
    u64 r; asm("mov.b64 %0, {%1, %1};" : "=l"(r) : "f"(v)); return r;
}
__device__ __forceinline__ u64 pack2(float a, float b) {
    u64 r; asm("mov.b64 %0, {%1, %2};" : "=l"(r) : "f"(a), "f"(b)); return r;
}
__device__ __forceinline__ void unpack2(u64 v, float& a, float& b) {
    asm("mov.b64 {%0, %1}, %2;" : "=f"(a), "=f"(b) : "l"(v));
}
__device__ __forceinline__ u64 fma2(u64 a, u64 b, u64 c) {
    u64 d; asm("fma.rn.f32x2 %0, %1, %2, %3;" : "=l"(d) : "l"(a), "l"(b), "l"(c));
    return d;
}
__device__ __forceinline__ void split2(float f0, float f1, u32& hi, u32& lo) {
    __half h0 = __float2half_rn(f0), h1 = __float2half_rn(f1);
    __half2 hh = __halves2half2(h0, h1);
    hi = reinterpret_cast<u32&>(hh);
    __half2 ll = __floats2half2_rn(f0 - __half2float(h0),
                                   f1 - __half2float(h1));
    lo = reinterpret_cast<u32&>(ll);
}
__device__ __forceinline__ u32 hi2only(float f0, float f1) {
    __half2 hh = __floats2half2_rn(f0, f1);
    return reinterpret_cast<u32&>(hh);
}
__device__ __forceinline__ void mma16816(float d[4], u32 a0, u32 a1, u32 a2,
                                         u32 a3, u32 b0, u32 b1) {
    asm volatile(
        "mma.sync.aligned.m16n8k16.row.col.f32.f16.f16.f32 "
        "{%0,%1,%2,%3}, {%4,%5,%6,%7}, {%8,%9}, {%0,%1,%2,%3};"
        : "+f"(d[0]), "+f"(d[1]), "+f"(d[2]), "+f"(d[3])
        : "r"(a0), "r"(a1), "r"(a2), "r"(a3), "r"(b0), "r"(b1));
}
__device__ __forceinline__ void mma1688(float d[4], u32 a0, u32 a1, u32 b0) {
    asm volatile(
        "mma.sync.aligned.m16n8k8.row.col.f32.f16.f16.f32 "
        "{%0,%1,%2,%3}, {%4,%5}, {%6}, {%0,%1,%2,%3};"
        : "+f"(d[0]), "+f"(d[1]), "+f"(d[2]), "+f"(d[3])
        : "r"(a0), "r"(a1), "r"(b0));
}

__global__ void __launch_bounds__(kThreads, 2)
fsim_mma(const float* __restrict__ proj, const float* __restrict__ idm,
         const float* __restrict__ merg, const float* __restrict__ W1,
         const float* __restrict__ b1,   const float* __restrict__ W2,
         const float* __restrict__ b2,   const float* __restrict__ W3,
         const float* __restrict__ b3,   const float* __restrict__ smean,
         const float* __restrict__ svar, float* __restrict__ out)
{
    extern __shared__ char smem[];
    float* smf = (float*)smem;

    const int tid = threadIdx.x, w = tid >> 5, lane = tid & 31;
    const int g = lane >> 2, q = lane & 3;
    const int bx = blockIdx.x;

    // ---------------- phase A: stage W1[0:64] natural + tables -------------
    for (int i = tid; i < 64 * kH; i += kThreads)
        smf[(OFF_W1P >> 2) + i] = W1[i];
    if (tid < 64) {
        int c = tid * 2;
        float4 v;
        v.x = b2[c]; v.y = b2[c + 1]; v.z = W3[c]; v.w = W3[c + 1];
        *(float4*)(smem + OFF_BW + tid * 16) = v;
    }
    if (tid < 128)
        smf[(OFF_W72 >> 2) + tid] = W1[(size_t)72 * 128 + tid];
    __syncthreads();

    // -------- phase B: projAcc = proj@W1[:64]+b1 -> fragment-native fp32 ---
    // slots for this CTA: tileId(slot) = slot*GRID + bx (slot = 0..7)
    for (int task = tid; task < 1024; task += kThreads) {
        int t_s = task >> 7, rem = task & 127;
        int lr = rem >> 3, cg = rem & 7;      // row-in-tile, 16-col group
        int tileId = t_s * GRID + bx;
        if (tileId >= NT) continue;
        const float* prow = proj + (size_t)(tileId * 16 + lr) * 64;
        u64 acc[8];
        #pragma unroll
        for (int e = 0; e < 8; e++)
            acc[e] = pack2(__ldg(&b1[cg * 16 + 2 * e]),
                           __ldg(&b1[cg * 16 + 2 * e + 1]));
        #pragma unroll 4
        for (int k4 = 0; k4 < 16; k4++) {
            float4 av = __ldg((const float4*)(prow + k4 * 4));
            float avv[4] = {av.x, av.y, av.z, av.w};
            #pragma unroll
            for (int e2 = 0; e2 < 4; e2++) {
                u64 a = pack_dup(avv[e2]);
                const u64* ww = (const u64*)
                    &smf[(OFF_W1P >> 2) + (k4 * 4 + e2) * 128 + cg * 16];
                #pragma unroll
                for (int e = 0; e < 8; e++) acc[e] = fma2(a, ww[e], acc[e]);
            }
        }
        int half = (lr >> 3) & 1, lrow = lr & 7;
        #pragma unroll
        for (int e = 0; e < 8; e++) {
            int nf1 = cg * 2 + (e >> 2);
            int ln  = lrow * 4 + (e & 3);
            float lo_, hi_;
            unpack2(acc[e], lo_, hi_);
            *(float2*)(smem + OFF_PACC +
                       (size_t)(((t_s * 16 + nf1) * 32 + ln) * 16) + half * 8)
                = make_float2(lo_, hi_);
        }
    }
    __syncthreads();

    // ---- phase C: W2 -> hi-only frags packed per nf-pair (overwrites W1P) -
    for (int i = tid; i < 2048; i += kThreads) {
        int t  = i & 31, nf2 = (i >> 5) & 7, kb = (i >> 8) & 7;
        int gg = t >> 2, qq = t & 3;
        int k0 = kb * 16 + qq * 2;
        int nA = nf2 * 16 + gg;
        int nB = nA + 8;
        u32 hA0 = hi2only(W2[(size_t)k0 * 128 + nA],
                          W2[(size_t)(k0 + 1) * 128 + nA]);
        u32 hA1 = hi2only(W2[(size_t)(k0 + 8) * 128 + nA],
                          W2[(size_t)(k0 + 9) * 128 + nA]);
        u32 hB0 = hi2only(W2[(size_t)k0 * 128 + nB],
                          W2[(size_t)(k0 + 1) * 128 + nB]);
        u32 hB1 = hi2only(W2[(size_t)(k0 + 8) * 128 + nB],
                          W2[(size_t)(k0 + 9) * 128 + nB]);
        ulonglong2 e;
        e.x = ((u64)hA1 << 32) | hA0;
        e.y = ((u64)hB1 << 32) | hB0;
        *(ulonglong2*)(smem + OFF_BFRAG +
                       (size_t)((kb * 8 + nf2) * 32 + t) * 16) = e;
    }
    // -------- phase C2: W1e rows 64..71 -> k8 B-frags [hi u32 | lo u32] ----
    for (int i = tid; i < 512; i += kThreads) {
        int t = i & 31, nf = i >> 5;        // nf1 0..15
        int gg = t >> 2, qq = t & 3;
        int n  = nf * 8 + gg;
        int k0 = qq * 2;
        float w00 = W1[(size_t)(64 + k0) * 128 + n];
        float w01 = W1[(size_t)(64 + k0 + 1) * 128 + n];
        u32 h, l;
        split2(w00, w01, h, l);
        *(u64*)(smem + OFF_W1EB + (size_t)(nf * 32 + t) * 8) =
            ((u64)l << 32) | h;
    }
    __syncthreads();

    // -------- warp tile via SMSP-balanced slot rotation; inactive exit -----
    const int slot   = (w + bx) & 7;
    const int tileId = slot * GRID + bx;
    if (tileId >= NT) return;

    const float b3v = __ldg(&b3[0]);
    const int gr0 = tileId * 16 + g;           // this lane's two rows
    const int gr1 = gr0 + 8;
    // scaler consts for features j = 2q, 2q+1 (q==3 -> mc passthrough)
    float scm0 = 0.f, scm1 = 0.f, sci0 = 1.f, sci1 = 1.f;
    if (q < 3) {
        scm0 = __ldg(&smean[2 * q]);
        scm1 = __ldg(&smean[2 * q + 1]);
        sci0 = rsqrtf(__ldg(&svar[2 * q]));
        sci1 = rsqrtf(__ldg(&svar[2 * q + 1]));
    }

    // carry + prefetch (per lane, both rows; redundant over q — no comms)
    float egv[2], egx[2], act[2] = {0.f, 0.f};
    float4 pa[2];
    float ps4[2], ps5[2], ps11[2], pm0[2], pm1[2], pm2[2];
    #pragma unroll
    for (int i = 0; i < 2; i++) {
        int gr = (i == 0) ? gr0 : gr1;
        const float* sp = idm + (size_t)gr * (kT * 12);
        pa[i] = __ldg((const float4*)sp);
        float2 s45 = __ldg((const float2*)(sp + 4));
        ps4[i] = s45.x; ps5[i] = s45.y;
        ps11[i] = __ldg(sp + 11);
        const float* mp = merg + (size_t)gr * (kT * 3);
        pm0[i] = __ldg(mp); pm1[i] = __ldg(mp + 1); pm2[i] = __ldg(mp + 2);
    }

    // ================= timestep loop (warp-local, no barriers) =============
    for (int t = 0; t < kT; t++) {
        // ---- env features + A-fragments, in registers ----
        u32 ehi[2], elo[2];
        float e8v[2];
        #pragma unroll
        for (int i = 0; i < 2; i++) {
            if (t == 0) { egv[i] = pa[i].x; egx[i] = pa[i].w; }
            else {
                egv[i] = fmaf(act[i], 0.1f, egv[i]);
                egx[i] = egx[i] + egv[i] * 0.1f + act[i] * 0.005f;
            }
            float f0 = egv[i];
            float f1 = pa[i].y;
            float f2 = egv[i] - pa[i].y;
            float f3 = ps4[i] - egx[i];
            float f4 = (egv[i] - pa[i].z) * ps11[i];
            float f5 = (ps5[i] - egx[i]) * ps11[i] + (1.0f - ps11[i]) * 100.0f;
            float fa, fb;
            if      (q == 0) { fa = f0; fb = f1; }
            else if (q == 1) { fa = f2; fb = f3; }
            else if (q == 2) { fa = f4; fb = f5; }
            else             { fa = pm0[i]; fb = pm1[i]; }
            fa = (fa - scm0) * sci0;
            fb = (fb - scm1) * sci1;
            split2(fa, fb, ehi[i], elo[i]);
            e8v[i] = pm2[i];
        }

        // ---- prefetch t+1 (hidden under the mma phase) ----
        if (t + 1 < kT) {
            #pragma unroll
            for (int i = 0; i < 2; i++) {
                int gr = (i == 0) ? gr0 : gr1;
                const float* sp = idm + (size_t)gr * (kT * 12) + (t + 1) * 12;
                pa[i] = __ldg((const float4*)sp);
                float2 s45 = __ldg((const float2*)(sp + 4));
                ps4[i] = s45.x; ps5[i] = s45.y;
                ps11[i] = __ldg(sp + 11);
                const float* mp = merg + (size_t)gr * (kT * 3) + (t + 1) * 3;
                pm0[i] = __ldg(mp); pm1[i] = __ldg(mp + 1); pm2[i] = __ldg(mp + 2);
            }
        }

        float d[16][4];
        #pragma unroll
        for (int nf = 0; nf < 16; nf++)
            d[nf][0] = d[nf][1] = d[nf][2] = d[nf][3] = 0.f;

        for (int kb = 0; kb < 8; kb++) {
            // ---- GEMM1 (k8, 3-term) + exact feature-8 FMA ----
            int nf1 = kb * 2;
            float4 pv0 = *(const float4*)(smem + OFF_PACC +
                (size_t)(((slot * 16 + nf1) * 32 + lane) * 16));
            float4 pv1 = *(const float4*)(smem + OFF_PACC +
                (size_t)(((slot * 16 + nf1 + 1) * 32 + lane) * 16));
            u64 bA = *(const u64*)(smem + OFF_W1EB +
                (size_t)((nf1 * 32 + lane) * 8));
            u64 bB = *(const u64*)(smem + OFF_W1EB +
                (size_t)(((nf1 + 1) * 32 + lane) * 8));
            float2 wA = *(const float2*)(smem + OFF_W72 + (nf1 * 4 + q) * 8);
            float2 wB = *(const float2*)(smem + OFF_W72 + ((nf1 + 1) * 4 + q) * 8);
            float dd[2][4];
            dd[0][0] = fmaf(e8v[0], wA.x, pv0.x);
            dd[0][1] = fmaf(e8v[0], wA.y, pv0.y);
            dd[0][2] = fmaf(e8v[1], wA.x, pv0.z);
            dd[0][3] = fmaf(e8v[1], wA.y, pv0.w);
            dd[1][0] = fmaf(e8v[0], wB.x, pv1.x);
            dd[1][1] = fmaf(e8v[0], wB.y, pv1.y);
            dd[1][2] = fmaf(e8v[1], wB.x, pv1.z);
            dd[1][3] = fmaf(e8v[1], wB.y, pv1.w);
            u32 hA = (u32)bA, lA = (u32)(bA >> 32);
            u32 hB = (u32)bB, lB = (u32)(bB >> 32);
            mma1688(dd[0], ehi[0], ehi[1], hA);
            mma1688(dd[1], ehi[0], ehi[1], hB);
            mma1688(dd[0], elo[0], elo[1], hA);   // lo*hi
            mma1688(dd[1], elo[0], elo[1], hB);
            mma1688(dd[0], ehi[0], ehi[1], lA);   // hi*lo
            mma1688(dd[1], ehi[0], ehi[1], lB);

            u32 Ah[4], Al[4];
            #pragma unroll
            for (int nfo = 0; nfo < 2; nfo++) {
                u32 h01, l01, h23, l23;
                split2(fmaxf(dd[nfo][0], 0.f), fmaxf(dd[nfo][1], 0.f), h01, l01);
                split2(fmaxf(dd[nfo][2], 0.f), fmaxf(dd[nfo][3], 0.f), h23, l23);
                Ah[nfo * 2 + 0] = h01;  Al[nfo * 2 + 0] = l01;
                Ah[nfo * 2 + 1] = h23;  Al[nfo * 2 + 1] = l23;
            }

            // ---- GEMM2 (2-term): 128 cols via 8 nf-pairs ----
            const char* bfp = smem + OFF_BFRAG +
                              (size_t)(kb * 8) * 512 + lane * 16;
            #pragma unroll
            for (int nf2 = 0; nf2 < 8; nf2++) {
                ulonglong2 bf = *(const ulonglong2*)(bfp + nf2 * 512);
                u32 hA0 = (u32)bf.x, hA1 = (u32)(bf.x >> 32);
                u32 hB0 = (u32)bf.y, hB1 = (u32)(bf.y >> 32);
                mma16816(d[2 * nf2],     Ah[0], Ah[1], Ah[2], Ah[3], hA0, hA1);
                mma16816(d[2 * nf2 + 1], Ah[0], Ah[1], Ah[2], Ah[3], hB0, hB1);
                mma16816(d[2 * nf2],     Al[0], Al[1], Al[2], Al[3], hA0, hA1);
                mma16816(d[2 * nf2 + 1], Al[0], Al[1], Al[2], Al[3], hB0, hB1);
            }
        }

        // ---- epilogue: relu(D + b2) . W3 ; per-lane rows via shfl-xor ----
        float s0 = 0.f, s1 = 0.f;
        #pragma unroll
        for (int nf = 0; nf < 16; nf++) {
            float4 bw = *(const float4*)(smem + OFF_BW + (nf * 4 + q) * 16);
            s0 += fmaxf(d[nf][0] + bw.x, 0.f) * bw.z +
                  fmaxf(d[nf][1] + bw.y, 0.f) * bw.w;
            s1 += fmaxf(d[nf][2] + bw.x, 0.f) * bw.z +
                  fmaxf(d[nf][3] + bw.y, 0.f) * bw.w;
        }
        s0 += __shfl_xor_sync(0xFFFFFFFFu, s0, 1);
        s0 += __shfl_xor_sync(0xFFFFFFFFu, s0, 2);
        s1 += __shfl_xor_sync(0xFFFFFFFFu, s1, 1);
        s1 += __shfl_xor_sync(0xFFFFFFFFu, s1, 2);
        act[0] = s0 + b3v;      // act(row gr0), identical in all q lanes
        act[1] = s1 + b3v;      // act(row gr1)
        if (q == 0) {
            out[(size_t)gr0 * kT + t] = act[0];
            out[(size_t)gr1 * kT + t] = act[1];
        }
    }
}

extern "C" void kernel_launch(void* const* d_in, const int* in_sizes, int n_in,
                              void* d_out, int out_size)
{
    (void)in_sizes; (void)n_in; (void)out_size;
    const float* proj  = (const float*)d_in[0];
    const float* idm   = (const float*)d_in[1];
    const float* merg  = (const float*)d_in[2];
    const float* W1    = (const float*)d_in[3];
    const float* b1    = (const float*)d_in[4];
    const float* W2    = (const float*)d_in[5];
    const float* b2    = (const float*)d_in[6];
    const float* W3    = (const float*)d_in[7];
    const float* b3    = (const float*)d_in[8];
    const float* smean = (const float*)d_in[9];
    const float* svar  = (const float*)d_in[10];
    float* out = (float*)d_out;

    cudaFuncSetAttribute(fsim_mma, cudaFuncAttributeMaxDynamicSharedMemorySize,
                         SMEM_BYTES);
    fsim_mma<<<GRID, kThreads, SMEM_BYTES>>>(
        proj, idm, merg, W1, b1, W2, b2, W3, b3, smean, svar, out);
}

// round 16
// speedup vs baseline: 1.2747x; 1.0357x over previous
#include <cuda_runtime.h>
#include <cuda_fp16.h>
#include <cstddef>

// ForwardSim, fully tensorized HMMA (sm_103 baseline mma.sync).
// R16 = R15/R12 + scheduling polish (no math/layout change):
//  (1) mma asm non-volatile (register deps only) so ptxas can interleave
//      mmas and hoist LDS loads across them;
//  (2) BFRAG loads per kb explicitly hoisted above the GEMM1 chain;
//  (3) epilogue tree reduction (2 independent partials per row).
// Structure: warp-local 16-row pipelines, grid 296, 2 CTA/SM, no barriers;
// GEMM2 2-term fp16 split (A hi+lo, B hi-only); GEMM1 k8 3-term + exact
// fp32 feature-8 FMA; idm/merg prefetch.

using u32 = unsigned int;
using u64 = unsigned long long;

namespace {
constexpr int kB = 32768, kT = 50, kH = 128, kThreads = 256;
constexpr int GRID = 296;            // 2 x 148 SMs
constexpr int NT   = kB / 16;        // 2048 warp-tiles of 16 rows

constexpr int OFF_BFRAG = 0;        // 32768: W2 hi frags [kb][nf2][lane] 16B
constexpr int OFF_PACC  = 32768;    // 65536: projAcc frags [slot][nf1][lane] 16B
constexpr int OFF_W1EB  = 98304;    // 4096:  W1e k8 B-frags [nf1][lane] 8B
constexpr int OFF_W72   = 102400;   // 512:   W1 row 72 natural
constexpr int OFF_BW    = 102912;   // 1024:  (b2 pair, W3 pair) per col pair
constexpr int SMEM_BYTES = 103936;
constexpr int OFF_W1P   = 0;        // phase alias in BFRAG: W1[0:64] natural
} // namespace

__device__ __forceinline__ u64 pack_dup(float v) {
    u64 r; asm("mov.b64 %0, {%1, %1};" : "=l"(r) : "f"(v)); return r;
}
__device__ __forceinline__ u64 pack2(float a, float b) {
    u64 r; asm("mov.b64 %0, {%1, %2};" : "=l"(r) : "f"(a), "f"(b)); return r;
}
__device__ __forceinline__ void unpack2(u64 v, float& a, float& b) {
    asm("mov.b64 {%0, %1}, %2;" : "=f"(a), "=f"(b) : "l"(v));
}
__device__ __forceinline__ u64 fma2(u64 a, u64 b, u64 c) {
    u64 d; asm("fma.rn.f32x2 %0, %1, %2, %3;" : "=l"(d) : "l"(a), "l"(b), "l"(c));
    return d;
}
__device__ __forceinline__ void split2(float f0, float f1, u32& hi, u32& lo) {
    __half h0 = __float2half_rn(f0), h1 = __float2half_rn(f1);
    __half2 hh = __halves2half2(h0, h1);
    hi = reinterpret_cast<u32&>(hh);
    __half2 ll = __floats2half2_rn(f0 - __half2float(h0),
                                   f1 - __half2float(h1));
    lo = reinterpret_cast<u32&>(ll);
}
__device__ __forceinline__ u32 hi2only(float f0, float f1) {
    __half2 hh = __floats2half2_rn(f0, f1);
    return reinterpret_cast<u32&>(hh);
}
// NOTE: non-volatile. Register constraints carry all dependencies; letting
// the compiler schedule these is the point of R16.
__device__ __forceinline__ void mma16816(float d[4], u32 a0, u32 a1, u32 a2,
                                         u32 a3, u32 b0, u32 b1) {
    asm("mma.sync.aligned.m16n8k16.row.col.f32.f16.f16.f32 "
        "{%0,%1,%2,%3}, {%4,%5,%6,%7}, {%8,%9}, {%0,%1,%2,%3};"
        : "+f"(d[0]), "+f"(d[1]), "+f"(d[2]), "+f"(d[3])
        : "r"(a0), "r"(a1), "r"(a2), "r"(a3), "r"(b0), "r"(b1));
}
__device__ __forceinline__ void mma1688(float d[4], u32 a0, u32 a1, u32 b0) {
    asm("mma.sync.aligned.m16n8k8.row.col.f32.f16.f16.f32 "
        "{%0,%1,%2,%3}, {%4,%5}, {%6}, {%0,%1,%2,%3};"
        : "+f"(d[0]), "+f"(d[1]), "+f"(d[2]), "+f"(d[3])
        : "r"(a0), "r"(a1), "r"(b0));
}

__global__ void __launch_bounds__(kThreads, 2)
fsim_mma(const float* __restrict__ proj, const float* __restrict__ idm,
         const float* __restrict__ merg, const float* __restrict__ W1,
         const float* __restrict__ b1,   const float* __restrict__ W2,
         const float* __restrict__ b2,   const float* __restrict__ W3,
         const float* __restrict__ b3,   const float* __restrict__ smean,
         const float* __restrict__ svar, float* __restrict__ out)
{
    extern __shared__ char smem[];
    float* smf = (float*)smem;

    const int tid = threadIdx.x, w = tid >> 5, lane = tid & 31;
    const int g = lane >> 2, q = lane & 3;
    const int bx = blockIdx.x;

    // ---------------- phase A: stage W1[0:64] natural + tables -------------
    for (int i = tid; i < 64 * kH; i += kThreads)
        smf[(OFF_W1P >> 2) + i] = W1[i];
    if (tid < 64) {
        int c = tid * 2;
        float4 v;
        v.x = b2[c]; v.y = b2[c + 1]; v.z = W3[c]; v.w = W3[c + 1];
        *(float4*)(smem + OFF_BW + tid * 16) = v;
    }
    if (tid < 128)
        smf[(OFF_W72 >> 2) + tid] = W1[(size_t)72 * 128 + tid];
    __syncthreads();

    // -------- phase B: projAcc = proj@W1[:64]+b1 -> fragment-native fp32 ---
    for (int task = tid; task < 1024; task += kThreads) {
        int t_s = task >> 7, rem = task & 127;
        int lr = rem >> 3, cg = rem & 7;      // row-in-tile, 16-col group
        int tileId = t_s * GRID + bx;
        if (tileId >= NT) continue;
        const float* prow = proj + (size_t)(tileId * 16 + lr) * 64;
        u64 acc[8];
        #pragma unroll
        for (int e = 0; e < 8; e++)
            acc[e] = pack2(__ldg(&b1[cg * 16 + 2 * e]),
                           __ldg(&b1[cg * 16 + 2 * e + 1]));
        #pragma unroll 4
        for (int k4 = 0; k4 < 16; k4++) {
            float4 av = __ldg((const float4*)(prow + k4 * 4));
            float avv[4] = {av.x, av.y, av.z, av.w};
            #pragma unroll
            for (int e2 = 0; e2 < 4; e2++) {
                u64 a = pack_dup(avv[e2]);
                const u64* ww = (const u64*)
                    &smf[(OFF_W1P >> 2) + (k4 * 4 + e2) * 128 + cg * 16];
                #pragma unroll
                for (int e = 0; e < 8; e++) acc[e] = fma2(a, ww[e], acc[e]);
            }
        }
        int half = (lr >> 3) & 1, lrow = lr & 7;
        #pragma unroll
        for (int e = 0; e < 8; e++) {
            int nf1 = cg * 2 + (e >> 2);
            int ln  = lrow * 4 + (e & 3);
            float lo_, hi_;
            unpack2(acc[e], lo_, hi_);
            *(float2*)(smem + OFF_PACC +
                       (size_t)(((t_s * 16 + nf1) * 32 + ln) * 16) + half * 8)
                = make_float2(lo_, hi_);
        }
    }
    __syncthreads();

    // ---- phase C: W2 -> hi-only frags packed per nf-pair (overwrites W1P) -
    for (int i = tid; i < 2048; i += kThreads) {
        int t  = i & 31, nf2 = (i >> 5) & 7, kb = (i >> 8) & 7;
        int gg = t >> 2, qq = t & 3;
        int k0 = kb * 16 + qq * 2;
        int nA = nf2 * 16 + gg;
        int nB = nA + 8;
        u32 hA0 = hi2only(W2[(size_t)k0 * 128 + nA],
                          W2[(size_t)(k0 + 1) * 128 + nA]);
        u32 hA1 = hi2only(W2[(size_t)(k0 + 8) * 128 + nA],
                          W2[(size_t)(k0 + 9) * 128 + nA]);
        u32 hB0 = hi2only(W2[(size_t)k0 * 128 + nB],
                          W2[(size_t)(k0 + 1) * 128 + nB]);
        u32 hB1 = hi2only(W2[(size_t)(k0 + 8) * 128 + nB],
                          W2[(size_t)(k0 + 9) * 128 + nB]);
        ulonglong2 e;
        e.x = ((u64)hA1 << 32) | hA0;
        e.y = ((u64)hB1 << 32) | hB0;
        *(ulonglong2*)(smem + OFF_BFRAG +
                       (size_t)((kb * 8 + nf2) * 32 + t) * 16) = e;
    }
    // -------- phase C2: W1e rows 64..71 -> k8 B-frags [hi u32 | lo u32] ----
    for (int i = tid; i < 512; i += kThreads) {
        int t = i & 31, nf = i >> 5;        // nf1 0..15
        int gg = t >> 2, qq = t & 3;
        int n  = nf * 8 + gg;
        int k0 = qq * 2;
        float w00 = W1[(size_t)(64 + k0) * 128 + n];
        float w01 = W1[(size_t)(64 + k0 + 1) * 128 + n];
        u32 h, l;
        split2(w00, w01, h, l);
        *(u64*)(smem + OFF_W1EB + (size_t)(nf * 32 + t) * 8) =
            ((u64)l << 32) | h;
    }
    __syncthreads();

    // -------- warp tile via SMSP-balanced slot rotation; inactive exit -----
    const int slot   = (w + bx) & 7;
    const int tileId = slot * GRID + bx;
    if (tileId >= NT) return;

    const float b3v = __ldg(&b3[0]);
    const int gr0 = tileId * 16 + g;           // this lane's two rows
    const int gr1 = gr0 + 8;
    // scaler consts for features j = 2q, 2q+1 (q==3 -> mc passthrough)
    float scm0 = 0.f, scm1 = 0.f, sci0 = 1.f, sci1 = 1.f;
    if (q < 3) {
        scm0 = __ldg(&smean[2 * q]);
        scm1 = __ldg(&smean[2 * q + 1]);
        sci0 = rsqrtf(__ldg(&svar[2 * q]));
        sci1 = rsqrtf(__ldg(&svar[2 * q + 1]));
    }

    // carry + prefetch (per lane, both rows; redundant over q — no comms)
    float egv[2], egx[2], act[2] = {0.f, 0.f};
    float4 pa[2];
    float ps4[2], ps5[2], ps11[2], pm0[2], pm1[2], pm2[2];
    #pragma unroll
    for (int i = 0; i < 2; i++) {
        int gr = (i == 0) ? gr0 : gr1;
        const float* sp = idm + (size_t)gr * (kT * 12);
        pa[i] = __ldg((const float4*)sp);
        float2 s45 = __ldg((const float2*)(sp + 4));
        ps4[i] = s45.x; ps5[i] = s45.y;
        ps11[i] = __ldg(sp + 11);
        const float* mp = merg + (size_t)gr * (kT * 3);
        pm0[i] = __ldg(mp); pm1[i] = __ldg(mp + 1); pm2[i] = __ldg(mp + 2);
    }

    // ================= timestep loop (warp-local, no barriers) =============
    for (int t = 0; t < kT; t++) {
        // ---- env features + A-fragments, in registers ----
        u32 ehi[2], elo[2];
        float e8v[2];
        #pragma unroll
        for (int i = 0; i < 2; i++) {
            if (t == 0) { egv[i] = pa[i].x; egx[i] = pa[i].w; }
            else {
                egv[i] = fmaf(act[i], 0.1f, egv[i]);
                egx[i] = egx[i] + egv[i] * 0.1f + act[i] * 0.005f;
            }
            float f0 = egv[i];
            float f1 = pa[i].y;
            float f2 = egv[i] - pa[i].y;
            float f3 = ps4[i] - egx[i];
            float f4 = (egv[i] - pa[i].z) * ps11[i];
            float f5 = (ps5[i] - egx[i]) * ps11[i] + (1.0f - ps11[i]) * 100.0f;
            float fa, fb;
            if      (q == 0) { fa = f0; fb = f1; }
            else if (q == 1) { fa = f2; fb = f3; }
            else if (q == 2) { fa = f4; fb = f5; }
            else             { fa = pm0[i]; fb = pm1[i]; }
            fa = (fa - scm0) * sci0;
            fb = (fb - scm1) * sci1;
            split2(fa, fb, ehi[i], elo[i]);
            e8v[i] = pm2[i];
        }

        // ---- prefetch t+1 (hidden under the mma phase) ----
        if (t + 1 < kT) {
            #pragma unroll
            for (int i = 0; i < 2; i++) {
                int gr = (i == 0) ? gr0 : gr1;
                const float* sp = idm + (size_t)gr * (kT * 12) + (t + 1) * 12;
                pa[i] = __ldg((const float4*)sp);
                float2 s45 = __ldg((const float2*)(sp + 4));
                ps4[i] = s45.x; ps5[i] = s45.y;
                ps11[i] = __ldg(sp + 11);
                const float* mp = merg + (size_t)gr * (kT * 3) + (t + 1) * 3;
                pm0[i] = __ldg(mp); pm1[i] = __ldg(mp + 1); pm2[i] = __ldg(mp + 2);
            }
        }

        float d[16][4];
        #pragma unroll
        for (int nf = 0; nf < 16; nf++)
            d[nf][0] = d[nf][1] = d[nf][2] = d[nf][3] = 0.f;

        #pragma unroll
        for (int kb = 0; kb < 8; kb++) {
            // ---- hoisted loads: B-frags for GEMM2 + GEMM1 operands --------
            const char* bfp = smem + OFF_BFRAG +
                              (size_t)(kb * 8) * 512 + lane * 16;
            ulonglong2 bf[8];
            #pragma unroll
            for (int nf2 = 0; nf2 < 8; nf2++)
                bf[nf2] = *(const ulonglong2*)(bfp + nf2 * 512);

            int nf1 = kb * 2;
            float4 pv0 = *(const float4*)(smem + OFF_PACC +
                (size_t)(((slot * 16 + nf1) * 32 + lane) * 16));
            float4 pv1 = *(const float4*)(smem + OFF_PACC +
                (size_t)(((slot * 16 + nf1 + 1) * 32 + lane) * 16));
            u64 bA = *(const u64*)(smem + OFF_W1EB +
                (size_t)((nf1 * 32 + lane) * 8));
            u64 bB = *(const u64*)(smem + OFF_W1EB +
                (size_t)(((nf1 + 1) * 32 + lane) * 8));
            float2 wA = *(const float2*)(smem + OFF_W72 + (nf1 * 4 + q) * 8);
            float2 wB = *(const float2*)(smem + OFF_W72 + ((nf1 + 1) * 4 + q) * 8);

            // ---- GEMM1 (k8, 3-term) + exact feature-8 FMA ----
            float dd[2][4];
            dd[0][0] = fmaf(e8v[0], wA.x, pv0.x);
            dd[0][1] = fmaf(e8v[0], wA.y, pv0.y);
            dd[0][2] = fmaf(e8v[1], wA.x, pv0.z);
            dd[0][3] = fmaf(e8v[1], wA.y, pv0.w);
            dd[1][0] = fmaf(e8v[0], wB.x, pv1.x);
            dd[1][1] = fmaf(e8v[0], wB.y, pv1.y);
            dd[1][2] = fmaf(e8v[1], wB.x, pv1.z);
            dd[1][3] = fmaf(e8v[1], wB.y, pv1.w);
            u32 hA = (u32)bA, lA = (u32)(bA >> 32);
            u32 hB = (u32)bB, lB = (u32)(bB >> 32);
            mma1688(dd[0], ehi[0], ehi[1], hA);
            mma1688(dd[1], ehi[0], ehi[1], hB);
            mma1688(dd[0], elo[0], elo[1], hA);   // lo*hi
            mma1688(dd[1], elo[0], elo[1], hB);
            mma1688(dd[0], ehi[0], ehi[1], lA);   // hi*lo
            mma1688(dd[1], ehi[0], ehi[1], lB);

            u32 Ah[4], Al[4];
            #pragma unroll
            for (int nfo = 0; nfo < 2; nfo++) {
                u32 h01, l01, h23, l23;
                split2(fmaxf(dd[nfo][0], 0.f), fmaxf(dd[nfo][1], 0.f), h01, l01);
                split2(fmaxf(dd[nfo][2], 0.f), fmaxf(dd[nfo][3], 0.f), h23, l23);
                Ah[nfo * 2 + 0] = h01;  Al[nfo * 2 + 0] = l01;
                Ah[nfo * 2 + 1] = h23;  Al[nfo * 2 + 1] = l23;
            }

            // ---- GEMM2 (2-term): 128 cols via 8 nf-pairs ----
            #pragma unroll
            for (int nf2 = 0; nf2 < 8; nf2++) {
                u32 hA0 = (u32)bf[nf2].x, hA1 = (u32)(bf[nf2].x >> 32);
                u32 hB0 = (u32)bf[nf2].y, hB1 = (u32)(bf[nf2].y >> 32);
                mma16816(d[2 * nf2],     Ah[0], Ah[1], Ah[2], Ah[3], hA0, hA1);
                mma16816(d[2 * nf2 + 1], Ah[0], Ah[1], Ah[2], Ah[3], hB0, hB1);
                mma16816(d[2 * nf2],     Al[0], Al[1], Al[2], Al[3], hA0, hA1);
                mma16816(d[2 * nf2 + 1], Al[0], Al[1], Al[2], Al[3], hB0, hB1);
            }
        }

        // ---- epilogue: relu(D + b2) . W3 ; tree-reduced partials ----
        float s0a = 0.f, s0b = 0.f, s1a = 0.f, s1b = 0.f;
        #pragma unroll
        for (int nf = 0; nf < 8; nf++) {
            float4 bwa = *(const float4*)(smem + OFF_BW + (nf * 4 + q) * 16);
            float4 bwb = *(const float4*)(smem + OFF_BW +
                                          ((nf + 8) * 4 + q) * 16);
            s0a += fmaxf(d[nf][0] + bwa.x, 0.f) * bwa.z +
                   fmaxf(d[nf][1] + bwa.y, 0.f) * bwa.w;
            s0b += fmaxf(d[nf + 8][0] + bwb.x, 0.f) * bwb.z +
                   fmaxf(d[nf + 8][1] + bwb.y, 0.f) * bwb.w;
            s1a += fmaxf(d[nf][2] + bwa.x, 0.f) * bwa.z +
                   fmaxf(d[nf][3] + bwa.y, 0.f) * bwa.w;
            s1b += fmaxf(d[nf + 8][2] + bwb.x, 0.f) * bwb.z +
                   fmaxf(d[nf + 8][3] + bwb.y, 0.f) * bwb.w;
        }
        float s0 = s0a + s0b;
        float s1 = s1a + s1b;
        s0 += __shfl_xor_sync(0xFFFFFFFFu, s0, 1);
        s0 += __shfl_xor_sync(0xFFFFFFFFu, s0, 2);
        s1 += __shfl_xor_sync(0xFFFFFFFFu, s1, 1);
        s1 += __shfl_xor_sync(0xFFFFFFFFu, s1, 2);
        act[0] = s0 + b3v;      // act(row gr0), identical in all q lanes
        act[1] = s1 + b3v;      // act(row gr1)
        if (q == 0) {
            out[(size_t)gr0 * kT + t] = act[0];
            out[(size_t)gr1 * kT + t] = act[1];
        }
    }
}

extern "C" void kernel_launch(void* const* d_in, const int* in_sizes, int n_in,
                              void* d_out, int out_size)
{
    (void)in_sizes; (void)n_in; (void)out_size;
    const float* proj  = (const float*)d_in[0];
    const float* idm   = (const float*)d_in[1];
    const float* merg  = (const float*)d_in[2];
    const float* W1    = (const float*)d_in[3];
    const float* b1    = (const float*)d_in[4];
    const float* W2    = (const float*)d_in[5];
    const float* b2    = (const float*)d_in[6];
    const float* W3    = (const float*)d_in[7];
    const float* b3    = (const float*)d_in[8];
    const float* smean = (const float*)d_in[9];
    const float* svar  = (const float*)d_in[10];
    float* out = (float*)d_out;

    cudaFuncSetAttribute(fsim_mma, cudaFuncAttributeMaxDynamicSharedMemorySize,
                         SMEM_BYTES);
    fsim_mma<<<GRID, kThreads, SMEM_BYTES>>>(
        proj, idm, merg, W1, b1, W2, b2, W3, b3, smean, svar, out);
}

// round 17
// speedup vs baseline: 1.3004x; 1.0201x over previous
#include <cuda_runtime.h>
#include <cuda_fp16.h>
#include <cstddef>

// ForwardSim, fully tensorized HMMA (sm_103 baseline mma.sync).
// R17 = R16 + epilogue algebra: d[nf] accumulators are SEEDED with b2
// fragments (mma accumulates onto C), so the epilogue drops 64 FADDs and
// the combined (b2,W3) float4 table splits into two compact float2 tables
// (same smem wavefronts, fewer issue slots). No other change.
// Structure: warp-local 16-row pipelines, grid 296, 2 CTA/SM, no barriers;
// GEMM2 2-term fp16 split (A hi+lo, B hi-only); GEMM1 k8 3-term + exact
// fp32 feature-8 FMA; idm/merg prefetch; non-volatile mma asm.

using u32 = unsigned int;
using u64 = unsigned long long;

namespace {
constexpr int kB = 32768, kT = 50, kH = 128, kThreads = 256;
constexpr int GRID = 296;            // 2 x 148 SMs
constexpr int NT   = kB / 16;        // 2048 warp-tiles of 16 rows

constexpr int OFF_BFRAG = 0;        // 32768: W2 hi frags [kb][nf2][lane] 16B
constexpr int OFF_PACC  = 32768;    // 65536: projAcc frags [slot][nf1][lane] 16B
constexpr int OFF_W1EB  = 98304;    // 4096:  W1e k8 B-frags [nf1][lane] 8B
constexpr int OFF_W72   = 102400;   // 512:   W1 row 72 natural
constexpr int OFF_B2F   = 102912;   // 512:   b2 col-pair table [nf][q] float2
constexpr int OFF_W3F   = 103424;   // 512:   W3 col-pair table [nf][q] float2
constexpr int SMEM_BYTES = 103936;
constexpr int OFF_W1P   = 0;        // phase alias in BFRAG: W1[0:64] natural
} // namespace

__device__ __forceinline__ u64 pack_dup(float v) {
    u64 r; asm("mov.b64 %0, {%1, %1};" : "=l"(r) : "f"(v)); return r;
}
__device__ __forceinline__ u64 pack2(float a, float b) {
    u64 r; asm("mov.b64 %0, {%1, %2};" : "=l"(r) : "f"(a), "f"(b)); return r;
}
__device__ __forceinline__ void unpack2(u64 v, float& a, float& b) {
    asm("mov.b64 {%0, %1}, %2;" : "=f"(a), "=f"(b) : "l"(v));
}
__device__ __forceinline__ u64 fma2(u64 a, u64 b, u64 c) {
    u64 d; asm("fma.rn.f32x2 %0, %1, %2, %3;" : "=l"(d) : "l"(a), "l"(b), "l"(c));
    return d;
}
__device__ __forceinline__ void split2(float f0, float f1, u32& hi, u32& lo) {
    __half h0 = __float2half_rn(f0), h1 = __float2half_rn(f1);
    __half2 hh = __halves2half2(h0, h1);
    hi = reinterpret_cast<u32&>(hh);
    __half2 ll = __floats2half2_rn(f0 - __half2float(h0),
                                   f1 - __half2float(h1));
    lo = reinterpret_cast<u32&>(ll);
}
__device__ __forceinline__ u32 hi2only(float f0, float f1) {
    __half2 hh = __floats2half2_rn(f0, f1);
    return reinterpret_cast<u32&>(hh);
}
// Non-volatile: register constraints carry all dependencies; the compiler
// is free to interleave mmas and hoist loads across them (R16 win).
__device__ __forceinline__ void mma16816(float d[4], u32 a0, u32 a1, u32 a2,
                                         u32 a3, u32 b0, u32 b1) {
    asm("mma.sync.aligned.m16n8k16.row.col.f32.f16.f16.f32 "
        "{%0,%1,%2,%3}, {%4,%5,%6,%7}, {%8,%9}, {%0,%1,%2,%3};"
        : "+f"(d[0]), "+f"(d[1]), "+f"(d[2]), "+f"(d[3])
        : "r"(a0), "r"(a1), "r"(a2), "r"(a3), "r"(b0), "r"(b1));
}
__device__ __forceinline__ void mma1688(float d[4], u32 a0, u32 a1, u32 b0) {
    asm("mma.sync.aligned.m16n8k8.row.col.f32.f16.f16.f32 "
        "{%0,%1,%2,%3}, {%4,%5}, {%6}, {%0,%1,%2,%3};"
        : "+f"(d[0]), "+f"(d[1]), "+f"(d[2]), "+f"(d[3])
        : "r"(a0), "r"(a1), "r"(b0));
}

__global__ void __launch_bounds__(kThreads, 2)
fsim_mma(const float* __restrict__ proj, const float* __restrict__ idm,
         const float* __restrict__ merg, const float* __restrict__ W1,
         const float* __restrict__ b1,   const float* __restrict__ W2,
         const float* __restrict__ b2,   const float* __restrict__ W3,
         const float* __restrict__ b3,   const float* __restrict__ smean,
         const float* __restrict__ svar, float* __restrict__ out)
{
    extern __shared__ char smem[];
    float* smf = (float*)smem;

    const int tid = threadIdx.x, w = tid >> 5, lane = tid & 31;
    const int g = lane >> 2, q = lane & 3;
    const int bx = blockIdx.x;

    // ---------------- phase A: stage W1[0:64] natural + tables -------------
    for (int i = tid; i < 64 * kH; i += kThreads)
        smf[(OFF_W1P >> 2) + i] = W1[i];
    if (tid < 64) {
        int nf = tid >> 2, qq = tid & 3;
        int c = nf * 8 + 2 * qq;
        *(float2*)(smem + OFF_B2F + tid * 8) = make_float2(b2[c], b2[c + 1]);
        *(float2*)(smem + OFF_W3F + tid * 8) = make_float2(W3[c], W3[c + 1]);
    }
    if (tid < 128)
        smf[(OFF_W72 >> 2) + tid] = W1[(size_t)72 * 128 + tid];
    __syncthreads();

    // -------- phase B: projAcc = proj@W1[:64]+b1 -> fragment-native fp32 ---
    for (int task = tid; task < 1024; task += kThreads) {
        int t_s = task >> 7, rem = task & 127;
        int lr = rem >> 3, cg = rem & 7;      // row-in-tile, 16-col group
        int tileId = t_s * GRID + bx;
        if (tileId >= NT) continue;
        const float* prow = proj + (size_t)(tileId * 16 + lr) * 64;
        u64 acc[8];
        #pragma unroll
        for (int e = 0; e < 8; e++)
            acc[e] = pack2(__ldg(&b1[cg * 16 + 2 * e]),
                           __ldg(&b1[cg * 16 + 2 * e + 1]));
        #pragma unroll 4
        for (int k4 = 0; k4 < 16; k4++) {
            float4 av = __ldg((const float4*)(prow + k4 * 4));
            float avv[4] = {av.x, av.y, av.z, av.w};
            #pragma unroll
            for (int e2 = 0; e2 < 4; e2++) {
                u64 a = pack_dup(avv[e2]);
                const u64* ww = (const u64*)
                    &smf[(OFF_W1P >> 2) + (k4 * 4 + e2) * 128 + cg * 16];
                #pragma unroll
                for (int e = 0; e < 8; e++) acc[e] = fma2(a, ww[e], acc[e]);
            }
        }
        int half = (lr >> 3) & 1, lrow = lr & 7;
        #pragma unroll
        for (int e = 0; e < 8; e++) {
            int nf1 = cg * 2 + (e >> 2);
            int ln  = lrow * 4 + (e & 3);
            float lo_, hi_;
            unpack2(acc[e], lo_, hi_);
            *(float2*)(smem + OFF_PACC +
                       (size_t)(((t_s * 16 + nf1) * 32 + ln) * 16) + half * 8)
                = make_float2(lo_, hi_);
        }
    }
    __syncthreads();

    // ---- phase C: W2 -> hi-only frags packed per nf-pair (overwrites W1P) -
    for (int i = tid; i < 2048; i += kThreads) {
        int t  = i & 31, nf2 = (i >> 5) & 7, kb = (i >> 8) & 7;
        int gg = t >> 2, qq = t & 3;
        int k0 = kb * 16 + qq * 2;
        int nA = nf2 * 16 + gg;
        int nB = nA + 8;
        u32 hA0 = hi2only(W2[(size_t)k0 * 128 + nA],
                          W2[(size_t)(k0 + 1) * 128 + nA]);
        u32 hA1 = hi2only(W2[(size_t)(k0 + 8) * 128 + nA],
                          W2[(size_t)(k0 + 9) * 128 + nA]);
        u32 hB0 = hi2only(W2[(size_t)k0 * 128 + nB],
                          W2[(size_t)(k0 + 1) * 128 + nB]);
        u32 hB1 = hi2only(W2[(size_t)(k0 + 8) * 128 + nB],
                          W2[(size_t)(k0 + 9) * 128 + nB]);
        ulonglong2 e;
        e.x = ((u64)hA1 << 32) | hA0;
        e.y = ((u64)hB1 << 32) | hB0;
        *(ulonglong2*)(smem + OFF_BFRAG +
                       (size_t)((kb * 8 + nf2) * 32 + t) * 16) = e;
    }
    // -------- phase C2: W1e rows 64..71 -> k8 B-frags [hi u32 | lo u32] ----
    for (int i = tid; i < 512; i += kThreads) {
        int t = i & 31, nf = i >> 5;        // nf1 0..15
        int gg = t >> 2, qq = t & 3;
        int n  = nf * 8 + gg;
        int k0 = qq * 2;
        float w00 = W1[(size_t)(64 + k0) * 128 + n];
        float w01 = W1[(size_t)(64 + k0 + 1) * 128 + n];
        u32 h, l;
        split2(w00, w01, h, l);
        *(u64*)(smem + OFF_W1EB + (size_t)(nf * 32 + t) * 8) =
            ((u64)l << 32) | h;
    }
    __syncthreads();

    // -------- warp tile via SMSP-balanced slot rotation; inactive exit -----
    const int slot   = (w + bx) & 7;
    const int tileId = slot * GRID + bx;
    if (tileId >= NT) return;

    const float b3v = __ldg(&b3[0]);
    const int gr0 = tileId * 16 + g;           // this lane's two rows
    const int gr1 = gr0 + 8;
    // scaler consts for features j = 2q, 2q+1 (q==3 -> mc passthrough)
    float scm0 = 0.f, scm1 = 0.f, sci0 = 1.f, sci1 = 1.f;
    if (q < 3) {
        scm0 = __ldg(&smean[2 * q]);
        scm1 = __ldg(&smean[2 * q + 1]);
        sci0 = rsqrtf(__ldg(&svar[2 * q]));
        sci1 = rsqrtf(__ldg(&svar[2 * q + 1]));
    }

    // carry + prefetch (per lane, both rows; redundant over q — no comms)
    float egv[2], egx[2], act[2] = {0.f, 0.f};
    float4 pa[2];
    float ps4[2], ps5[2], ps11[2], pm0[2], pm1[2], pm2[2];
    #pragma unroll
    for (int i = 0; i < 2; i++) {
        int gr = (i == 0) ? gr0 : gr1;
        const float* sp = idm + (size_t)gr * (kT * 12);
        pa[i] = __ldg((const float4*)sp);
        float2 s45 = __ldg((const float2*)(sp + 4));
        ps4[i] = s45.x; ps5[i] = s45.y;
        ps11[i] = __ldg(sp + 11);
        const float* mp = merg + (size_t)gr * (kT * 3);
        pm0[i] = __ldg(mp); pm1[i] = __ldg(mp + 1); pm2[i] = __ldg(mp + 2);
    }

    // ================= timestep loop (warp-local, no barriers) =============
    for (int t = 0; t < kT; t++) {
        // ---- env features + A-fragments, in registers ----
        u32 ehi[2], elo[2];
        float e8v[2];
        #pragma unroll
        for (int i = 0; i < 2; i++) {
            if (t == 0) { egv[i] = pa[i].x; egx[i] = pa[i].w; }
            else {
                egv[i] = fmaf(act[i], 0.1f, egv[i]);
                egx[i] = egx[i] + egv[i] * 0.1f + act[i] * 0.005f;
            }
            float f0 = egv[i];
            float f1 = pa[i].y;
            float f2 = egv[i] - pa[i].y;
            float f3 = ps4[i] - egx[i];
            float f4 = (egv[i] - pa[i].z) * ps11[i];
            float f5 = (ps5[i] - egx[i]) * ps11[i] + (1.0f - ps11[i]) * 100.0f;
            float fa, fb;
            if      (q == 0) { fa = f0; fb = f1; }
            else if (q == 1) { fa = f2; fb = f3; }
            else if (q == 2) { fa = f4; fb = f5; }
            else             { fa = pm0[i]; fb = pm1[i]; }
            fa = (fa - scm0) * sci0;
            fb = (fb - scm1) * sci1;
            split2(fa, fb, ehi[i], elo[i]);
            e8v[i] = pm2[i];
        }

        // ---- prefetch t+1 (hidden under the mma phase) ----
        if (t + 1 < kT) {
            #pragma unroll
            for (int i = 0; i < 2; i++) {
                int gr = (i == 0) ? gr0 : gr1;
                const float* sp = idm + (size_t)gr * (kT * 12) + (t + 1) * 12;
                pa[i] = __ldg((const float4*)sp);
                float2 s45 = __ldg((const float2*)(sp + 4));
                ps4[i] = s45.x; ps5[i] = s45.y;
                ps11[i] = __ldg(sp + 11);
                const float* mp = merg + (size_t)gr * (kT * 3) + (t + 1) * 3;
                pm0[i] = __ldg(mp); pm1[i] = __ldg(mp + 1); pm2[i] = __ldg(mp + 2);
            }
        }

        // ---- d accumulators seeded with b2 (epilogue add folded in) ----
        float d[16][4];
        #pragma unroll
        for (int nf = 0; nf < 16; nf++) {
            float2 bv = *(const float2*)(smem + OFF_B2F + (nf * 4 + q) * 8);
            d[nf][0] = bv.x; d[nf][1] = bv.y;
            d[nf][2] = bv.x; d[nf][3] = bv.y;
        }

        #pragma unroll
        for (int kb = 0; kb < 8; kb++) {
            // ---- hoisted loads: B-frags for GEMM2 + GEMM1 operands --------
            const char* bfp = smem + OFF_BFRAG +
                              (size_t)(kb * 8) * 512 + lane * 16;
            ulonglong2 bf[8];
            #pragma unroll
            for (int nf2 = 0; nf2 < 8; nf2++)
                bf[nf2] = *(const ulonglong2*)(bfp + nf2 * 512);

            int nf1 = kb * 2;
            float4 pv0 = *(const float4*)(smem + OFF_PACC +
                (size_t)(((slot * 16 + nf1) * 32 + lane) * 16));
            float4 pv1 = *(const float4*)(smem + OFF_PACC +
                (size_t)(((slot * 16 + nf1 + 1) * 32 + lane) * 16));
            u64 bA = *(const u64*)(smem + OFF_W1EB +
                (size_t)((nf1 * 32 + lane) * 8));
            u64 bB = *(const u64*)(smem + OFF_W1EB +
                (size_t)(((nf1 + 1) * 32 + lane) * 8));
            float2 wA = *(const float2*)(smem + OFF_W72 + (nf1 * 4 + q) * 8);
            float2 wB = *(const float2*)(smem + OFF_W72 + ((nf1 + 1) * 4 + q) * 8);

            // ---- GEMM1 (k8, 3-term) + exact feature-8 FMA ----
            float dd[2][4];
            dd[0][0] = fmaf(e8v[0], wA.x, pv0.x);
            dd[0][1] = fmaf(e8v[0], wA.y, pv0.y);
            dd[0][2] = fmaf(e8v[1], wA.x, pv0.z);
            dd[0][3] = fmaf(e8v[1], wA.y, pv0.w);
            dd[1][0] = fmaf(e8v[0], wB.x, pv1.x);
            dd[1][1] = fmaf(e8v[0], wB.y, pv1.y);
            dd[1][2] = fmaf(e8v[1], wB.x, pv1.z);
            dd[1][3] = fmaf(e8v[1], wB.y, pv1.w);
            u32 hA = (u32)bA, lA = (u32)(bA >> 32);
            u32 hB = (u32)bB, lB = (u32)(bB >> 32);
            mma1688(dd[0], ehi[0], ehi[1], hA);
            mma1688(dd[1], ehi[0], ehi[1], hB);
            mma1688(dd[0], elo[0], elo[1], hA);   // lo*hi
            mma1688(dd[1], elo[0], elo[1], hB);
            mma1688(dd[0], ehi[0], ehi[1], lA);   // hi*lo
            mma1688(dd[1], ehi[0], ehi[1], lB);

            u32 Ah[4], Al[4];
            #pragma unroll
            for (int nfo = 0; nfo < 2; nfo++) {
                u32 h01, l01, h23, l23;
                split2(fmaxf(dd[nfo][0], 0.f), fmaxf(dd[nfo][1], 0.f), h01, l01);
                split2(fmaxf(dd[nfo][2], 0.f), fmaxf(dd[nfo][3], 0.f), h23, l23);
                Ah[nfo * 2 + 0] = h01;  Al[nfo * 2 + 0] = l01;
                Ah[nfo * 2 + 1] = h23;  Al[nfo * 2 + 1] = l23;
            }

            // ---- GEMM2 (2-term): 128 cols via 8 nf-pairs ----
            #pragma unroll
            for (int nf2 = 0; nf2 < 8; nf2++) {
                u32 hA0 = (u32)bf[nf2].x, hA1 = (u32)(bf[nf2].x >> 32);
                u32 hB0 = (u32)bf[nf2].y, hB1 = (u32)(bf[nf2].y >> 32);
                mma16816(d[2 * nf2],     Ah[0], Ah[1], Ah[2], Ah[3], hA0, hA1);
                mma16816(d[2 * nf2 + 1], Ah[0], Ah[1], Ah[2], Ah[3], hB0, hB1);
                mma16816(d[2 * nf2],     Al[0], Al[1], Al[2], Al[3], hA0, hA1);
                mma16816(d[2 * nf2 + 1], Al[0], Al[1], Al[2], Al[3], hB0, hB1);
            }
        }

        // ---- epilogue: relu(d) . W3 (b2 already folded into d) ----
        float s0a = 0.f, s0b = 0.f, s1a = 0.f, s1b = 0.f;
        #pragma unroll
        for (int nf = 0; nf < 8; nf++) {
            float2 wa = *(const float2*)(smem + OFF_W3F + (nf * 4 + q) * 8);
            float2 wb = *(const float2*)(smem + OFF_W3F + ((nf + 8) * 4 + q) * 8);
            s0a += fmaxf(d[nf][0], 0.f) * wa.x + fmaxf(d[nf][1], 0.f) * wa.y;
            s0b += fmaxf(d[nf + 8][0], 0.f) * wb.x +
                   fmaxf(d[nf + 8][1], 0.f) * wb.y;
            s1a += fmaxf(d[nf][2], 0.f) * wa.x + fmaxf(d[nf][3], 0.f) * wa.y;
            s1b += fmaxf(d[nf + 8][2], 0.f) * wb.x +
                   fmaxf(d[nf + 8][3], 0.f) * wb.y;
        }
        float s0 = s0a + s0b;
        float s1 = s1a + s1b;
        s0 += __shfl_xor_sync(0xFFFFFFFFu, s0, 1);
        s0 += __shfl_xor_sync(0xFFFFFFFFu, s0, 2);
        s1 += __shfl_xor_sync(0xFFFFFFFFu, s1, 1);
        s1 += __shfl_xor_sync(0xFFFFFFFFu, s1, 2);
        act[0] = s0 + b3v;      // act(row gr0), identical in all q lanes
        act[1] = s1 + b3v;      // act(row gr1)
        if (q == 0) {
            out[(size_t)gr0 * kT + t] = act[0];
            out[(size_t)gr1 * kT + t] = act[1];
        }
    }
}

extern "C" void kernel_launch(void* const* d_in, const int* in_sizes, int n_in,
                              void* d_out, int out_size)
{
    (void)in_sizes; (void)n_in; (void)out_size;
    const float* proj  = (const float*)d_in[0];
    const float* idm   = (const float*)d_in[1];
    const float* merg  = (const float*)d_in[2];
    const float* W1    = (const float*)d_in[3];
    const float* b1    = (const float*)d_in[4];
    const float* W2    = (const float*)d_in[5];
    const float* b2    = (const float*)d_in[6];
    const float* W3    = (const float*)d_in[7];
    const float* b3    = (const float*)d_in[8];
    const float* smean = (const float*)d_in[9];
    const float* svar  = (const float*)d_in[10];
    float* out = (float*)d_out;

    cudaFuncSetAttribute(fsim_mma, cudaFuncAttributeMaxDynamicSharedMemorySize,
                         SMEM_BYTES);
    fsim_mma<<<GRID, kThreads, SMEM_BYTES>>>(
        proj, idm, merg, W1, b1, W2, b2, W3, b3, smean, svar, out);
}